// round 12
// baseline (speedup 1.0000x reference)
#include <cuda_runtime.h>
#include <cuda_bf16.h>
#include <cstdint>

#define BATCH 8
#define CCH   256
#define WID   4096
#define GROUPS 3

// fp32 scratch: qkv[g*256+o][b][j]
__device__ float g_qkv[(size_t)GROUPS * CCH * BATCH * WID];
// pre-split bf16 operands
__device__ __nv_bfloat16 g_xh[(size_t)BATCH * CCH * WID];
__device__ __nv_bfloat16 g_xl[(size_t)BATCH * CCH * WID];
__device__ __nv_bfloat16 g_wh[(size_t)GROUPS * CCH * CCH];
__device__ __nv_bfloat16 g_wl[(size_t)GROUPS * CCH * CCH];

// ---------------------------------------------------------------------------
__device__ __forceinline__ uint32_t sptr(const void* p) {
    return (uint32_t)__cvta_generic_to_shared(p);
}
__device__ __forceinline__ void split2(float f0, float f1, uint32_t& h, uint32_t& l) {
    __nv_bfloat16 h0 = __float2bfloat16(f0);
    __nv_bfloat16 h1 = __float2bfloat16(f1);
    __nv_bfloat16 l0 = __float2bfloat16(f0 - __bfloat162float(h0));
    __nv_bfloat16 l1 = __float2bfloat16(f1 - __bfloat162float(h1));
    h = (uint32_t)__bfloat16_as_ushort(h0) | ((uint32_t)__bfloat16_as_ushort(h1) << 16);
    l = (uint32_t)__bfloat16_as_ushort(l0) | ((uint32_t)__bfloat16_as_ushort(l1) << 16);
}
__device__ __forceinline__ void ldsm_x4(uint32_t addr, uint32_t* r) {
    asm volatile("ldmatrix.sync.aligned.m8n8.x4.shared.b16 {%0,%1,%2,%3}, [%4];"
                 : "=r"(r[0]), "=r"(r[1]), "=r"(r[2]), "=r"(r[3]) : "r"(addr));
}
__device__ __forceinline__ void ldsm_x4_t(uint32_t addr, uint32_t& r0, uint32_t& r1,
                                          uint32_t& r2, uint32_t& r3) {
    asm volatile("ldmatrix.sync.aligned.m8n8.x4.trans.shared.b16 {%0,%1,%2,%3}, [%4];"
                 : "=r"(r0), "=r"(r1), "=r"(r2), "=r"(r3) : "r"(addr));
}
__device__ __forceinline__ void mma16816(float* c, const uint32_t* a,
                                         uint32_t b0, uint32_t b1) {
    asm volatile(
        "mma.sync.aligned.m16n8k16.row.col.f32.bf16.bf16.f32 "
        "{%0,%1,%2,%3}, {%4,%5,%6,%7}, {%8,%9}, {%0,%1,%2,%3};"
        : "+f"(c[0]), "+f"(c[1]), "+f"(c[2]), "+f"(c[3])
        : "r"(a[0]), "r"(a[1]), "r"(a[2]), "r"(a[3]), "r"(b0), "r"(b1));
}
#define CP16(dst, src) \
    asm volatile("cp.async.cg.shared.global [%0], [%1], 16;" :: "r"(dst), "l"(src))
#define CP_COMMIT() asm volatile("cp.async.commit_group;")
#define CP_WAIT(n)  asm volatile("cp.async.wait_group %0;" :: "n"(n))

// ---------------------------------------------------------------------------
// Kernel 0: split fp32 -> bf16 hi/lo; parameterized x-range, optional W part.
// ---------------------------------------------------------------------------
#define NX4 (BATCH * CCH * WID / 4)   // 2097152 float4 in x
#define NW4 (CCH * CCH / 4)           // 16384 float4 per weight
#define NXQ (NX4 / 4)                 // 524288 (2 batches)

__global__ __launch_bounds__(256)
void convert_split(const float* __restrict__ x, const float* __restrict__ wq,
                   const float* __restrict__ wk, const float* __restrict__ wv,
                   int nx4, int xbase, int withW)
{
    int idx = blockIdx.x * 256 + threadIdx.x;
    if (idx < nx4) {
        int e = xbase + idx;
        float4 v = ((const float4*)x)[e];
        uint32_t h01, l01, h23, l23;
        split2(v.x, v.y, h01, l01);
        split2(v.z, v.w, h23, l23);
        ((uint2*)g_xh)[e] = make_uint2(h01, h23);
        ((uint2*)g_xl)[e] = make_uint2(l01, l23);
    } else if (withW) {
        int r = idx - nx4;
        if (r < 3 * NW4) {
            int g = r / NW4, e = r % NW4;
            const float* W = (g == 0) ? wq : (g == 1) ? wk : wv;
            float4 v = ((const float4*)W)[e];
            uint32_t h01, l01, h23, l23;
            split2(v.x, v.y, h01, l01);
            split2(v.z, v.w, h23, l23);
            ((uint2*)g_wh)[g * NW4 + e] = make_uint2(h01, h23);
            ((uint2*)g_wl)[g * NW4 + e] = make_uint2(l01, l23);
        }
    }
}

// ---------------------------------------------------------------------------
// Kernel 1: GEMM (R5 design), 3-stage cp.async, pass-major MMA.
// Stage (37888 B): Ah[128][40]@0, Al@10240, Bh[32][136]@20480, Bl@29184
// ---------------------------------------------------------------------------
#define STAGE_BYTES 37888
#define SMEM_GEMM   (3 * STAGE_BYTES)   // 113664

__device__ __forceinline__ void prefetch_chunk(
    char* s, int stage, int tid,
    const __nv_bfloat16* __restrict__ whg, const __nv_bfloat16* __restrict__ wlg,
    const __nv_bfloat16* __restrict__ xhb, const __nv_bfloat16* __restrict__ xlb,
    int kc, int j0)
{
    uint32_t base = sptr(s + stage * STAGE_BYTES);
    #pragma unroll
    for (int i = 0; i < 2; ++i) {
        int e = tid + i * 256;
        int row = e >> 2, seg = e & 3;
        uint32_t off = (uint32_t)(row * 40 + seg * 8) * 2;
        CP16(base + off,         whg + (size_t)row * CCH + kc + seg * 8);
        CP16(base + 10240 + off, wlg + (size_t)row * CCH + kc + seg * 8);
    }
    #pragma unroll
    for (int i = 0; i < 2; ++i) {
        int e = tid + i * 256;
        int row = e >> 4, seg = e & 15;
        uint32_t off = (uint32_t)(row * 136 + seg * 8) * 2;
        CP16(base + 20480 + off, xhb + (size_t)(kc + row) * WID + j0 + seg * 8);
        CP16(base + 29184 + off, xlb + (size_t)(kc + row) * WID + j0 + seg * 8);
    }
}

__global__ __launch_bounds__(256, 2)
void qkv_gemm_mma(int bb)
{
    extern __shared__ char smem[];

    const int nt = blockIdx.x;
    const int my = blockIdx.y;
    const int b  = blockIdx.z + bb;
    const int g  = my >> 1;
    const int m0g = (my & 1) * 128;
    const int j0 = nt * 128;

    const __nv_bfloat16* whg = g_wh + (size_t)g * CCH * CCH + (size_t)m0g * CCH;
    const __nv_bfloat16* wlg = g_wl + (size_t)g * CCH * CCH + (size_t)m0g * CCH;
    const __nv_bfloat16* xhb = g_xh + (size_t)b * CCH * WID;
    const __nv_bfloat16* xlb = g_xl + (size_t)b * CCH * WID;

    const int tid  = threadIdx.x;
    const int lane = tid & 31;
    const int wid  = tid >> 5;
    const int wm   = wid >> 2;
    const int wn   = wid & 3;
    const int ltt  = lane >> 3;
    const int ltr  = lane & 7;

    float acc[4][4][4];
    #pragma unroll
    for (int i = 0; i < 4; ++i)
        #pragma unroll
        for (int j = 0; j < 4; ++j)
            #pragma unroll
            for (int r = 0; r < 4; ++r) acc[i][j][r] = 0.f;

    prefetch_chunk(smem, 0, tid, whg, wlg, xhb, xlb, 0, j0);
    CP_COMMIT();
    prefetch_chunk(smem, 1, tid, whg, wlg, xhb, xlb, 32, j0);
    CP_COMMIT();

    #pragma unroll 1
    for (int kc8 = 0; kc8 < 8; ++kc8) {
        const int stage = kc8 % 3;
        if (kc8 < 7) { CP_WAIT(1); } else { CP_WAIT(0); }
        __syncthreads();

        const char* sbuf = smem + stage * STAGE_BYTES;
        const __nv_bfloat16* Ahp = (const __nv_bfloat16*)(sbuf);
        const __nv_bfloat16* Alp = (const __nv_bfloat16*)(sbuf + 10240);
        const __nv_bfloat16* Bhp = (const __nv_bfloat16*)(sbuf + 20480);
        const __nv_bfloat16* Blp = (const __nv_bfloat16*)(sbuf + 29184);

        #pragma unroll
        for (int ks = 0; ks < 2; ++ks) {
            const int kb = ks * 16;
            uint32_t bh[4][2], bl[4][2];
            #pragma unroll
            for (int np = 0; np < 2; ++np) {
                int krow = kb + (ltt & 1) * 8 + ltr;
                int ncol = wn * 32 + np * 16 + (ltt >> 1) * 8;
                ldsm_x4_t(sptr(Bhp + krow * 136 + ncol),
                          bh[np * 2][0], bh[np * 2][1], bh[np * 2 + 1][0], bh[np * 2 + 1][1]);
                ldsm_x4_t(sptr(Blp + krow * 136 + ncol),
                          bl[np * 2][0], bl[np * 2][1], bl[np * 2 + 1][0], bl[np * 2 + 1][1]);
            }
            uint32_t ah[4][4], al[4][4];
            #pragma unroll
            for (int ma = 0; ma < 4; ++ma) {
                int row = wm * 64 + ma * 16 + (ltt & 1) * 8 + ltr;
                int col = kb + (ltt >> 1) * 8;
                ldsm_x4(sptr(Ahp + row * 40 + col), ah[ma]);
                ldsm_x4(sptr(Alp + row * 40 + col), al[ma]);
            }
            #pragma unroll
            for (int ma = 0; ma < 4; ++ma)
                #pragma unroll
                for (int na = 0; na < 4; ++na)
                    mma16816(acc[ma][na], ah[ma], bh[na][0], bh[na][1]);
            #pragma unroll
            for (int ma = 0; ma < 4; ++ma)
                #pragma unroll
                for (int na = 0; na < 4; ++na)
                    mma16816(acc[ma][na], al[ma], bh[na][0], bh[na][1]);
            #pragma unroll
            for (int ma = 0; ma < 4; ++ma)
                #pragma unroll
                for (int na = 0; na < 4; ++na)
                    mma16816(acc[ma][na], ah[ma], bl[na][0], bl[na][1]);
        }
        __syncthreads();

        if (kc8 < 6) {
            prefetch_chunk(smem, (kc8 + 2) % 3, tid, whg, wlg, xhb, xlb, (kc8 + 2) * 32, j0);
            CP_COMMIT();
        }
    }

    #pragma unroll
    for (int ma = 0; ma < 4; ++ma) {
        int r0 = m0g + wm * 64 + ma * 16 + (lane >> 2);
        #pragma unroll
        for (int na = 0; na < 4; ++na) {
            int jj = j0 + wn * 32 + na * 8 + (lane & 3) * 2;
            float* d0 = g_qkv + ((size_t)(g * 256 + r0) * BATCH + b) * WID + jj;
            float* d1 = d0 + (size_t)8 * BATCH * WID;
            *(float2*)d0 = make_float2(acc[ma][na][0], acc[ma][na][1]);
            *(float2*)d1 = make_float2(acc[ma][na][2], acc[ma][na][3]);
        }
    }
}

// ---------------------------------------------------------------------------
// Kernel 2: windowed softmax, 8 outputs/thread, no max-sub, fast divide.
// Covers 2 batches starting at bb (1024 blocks per chunk).
// ---------------------------------------------------------------------------
__global__ __launch_bounds__(256)
void attn_window8(float* __restrict__ out, int bb)
{
    int t8 = blockIdx.x * 256 + threadIdx.x;
    int w  = (t8 & 511) * 8;
    int t  = (t8 >> 9) + bb * 256;   // b*256 + o
    int o  = t & 255;
    int b  = t >> 8;

    const float* Q = g_qkv + ((size_t)o * BATCH + b) * WID;
    const float* K = Q + (size_t)256 * BATCH * WID;
    const float* V = Q + (size_t)512 * BATCH * WID;

    const float4 z4 = make_float4(0.f, 0.f, 0.f, 0.f);
    float4 q0 = *(const float4*)(Q + w);
    float4 q1 = *(const float4*)(Q + w + 4);
    float4 km = (w >= 4)      ? *(const float4*)(K + w - 4) : z4;
    float4 k0 = *(const float4*)(K + w);
    float4 k1 = *(const float4*)(K + w + 4);
    float4 kp = (w + 8 < WID) ? *(const float4*)(K + w + 8) : z4;
    float4 vm = (w >= 4)      ? *(const float4*)(V + w - 4) : z4;
    float4 v0 = *(const float4*)(V + w);
    float4 v1 = *(const float4*)(V + w + 4);
    float4 vp = (w + 8 < WID) ? *(const float4*)(V + w + 8) : z4;

    float kk[14] = {km.y, km.z, km.w, k0.x, k0.y, k0.z, k0.w,
                    k1.x, k1.y, k1.z, k1.w, kp.x, kp.y, kp.z};
    float vv[14] = {vm.y, vm.z, vm.w, v0.x, v0.y, v0.z, v0.w,
                    v1.x, v1.y, v1.z, v1.w, vp.x, vp.y, vp.z};
    float qv[8]  = {q0.x, q0.y, q0.z, q0.w, q1.x, q1.y, q1.z, q1.w};

    float res[8];
    #pragma unroll
    for (int tt = 0; tt < 8; ++tt) {
        float sum = 0.f, accn = 0.f;
        #pragma unroll
        for (int i = 0; i < 7; ++i) {
            float e = __expf(qv[tt] * kk[tt + i]);
            sum += e;
            accn = fmaf(e, vv[tt + i], accn);
        }
        res[tt] = __fdividef(accn, sum);
    }
    float* dst = out + (size_t)t * WID + w;
    *(float4*)dst       = make_float4(res[0], res[1], res[2], res[3]);
    *(float4*)(dst + 4) = make_float4(res[4], res[5], res[6], res[7]);
}

// ---------------------------------------------------------------------------
// Stream context (created at load time; no device memory).
// ---------------------------------------------------------------------------
namespace {
struct StreamCtx {
    cudaStream_t s[3];        // chunks 1..3 (chunk 0 runs on the main stream)
    cudaEvent_t evFork, evConvW, evJoin[3];
    StreamCtx() {
        for (int i = 0; i < 3; ++i)
            cudaStreamCreateWithFlags(&s[i], cudaStreamNonBlocking);
        cudaEventCreateWithFlags(&evFork,  cudaEventDisableTiming);
        cudaEventCreateWithFlags(&evConvW, cudaEventDisableTiming);
        for (int i = 0; i < 3; ++i)
            cudaEventCreateWithFlags(&evJoin[i], cudaEventDisableTiming);
    }
};
StreamCtx g_sc;

cudaStream_t pick_main_stream() {
    cudaStreamCaptureStatus st = cudaStreamCaptureStatusNone;
    if (cudaStreamGetCaptureInfo(cudaStreamPerThread, &st) == cudaSuccess &&
        st == cudaStreamCaptureStatusActive)
        return cudaStreamPerThread;
    return cudaStreamLegacy;
}
} // namespace

// ---------------------------------------------------------------------------
extern "C" void kernel_launch(void* const* d_in, const int* in_sizes, int n_in,
                              void* d_out, int out_size)
{
    (void)in_sizes; (void)n_in; (void)out_size;
    const float* x  = (const float*)d_in[0];
    const float* wq = (const float*)d_in[1];
    const float* wk = (const float*)d_in[2];
    const float* wv = (const float*)d_in[3];
    float* out = (float*)d_out;

    cudaFuncSetAttribute(qkv_gemm_mma, cudaFuncAttributeMaxDynamicSharedMemorySize, SMEM_GEMM);

    cudaStream_t ms = pick_main_stream();

    // fork
    cudaEventRecord(g_sc.evFork, ms);
    for (int i = 0; i < 3; ++i)
        cudaStreamWaitEvent(g_sc.s[i], g_sc.evFork, 0);

    // chunk 0 conversion (includes W) on ms
    convert_split<<<(NXQ + 3 * NW4 + 255) / 256, 256, 0, ms>>>(
        x, wq, wk, wv, NXQ, 0, 1);
    cudaEventRecord(g_sc.evConvW, ms);

    // chunks 1..3 conversion on their streams (x only)
    for (int c = 1; c < 4; ++c)
        convert_split<<<NXQ / 256, 256, 0, g_sc.s[c - 1]>>>(
            x, wq, wk, wv, NXQ, c * NXQ, 0);

    // chunk 0 GEMM + attn on ms
    {
        dim3 grid(32, 6, 2);
        qkv_gemm_mma<<<grid, 256, SMEM_GEMM, ms>>>(0);
        attn_window8<<<1024, 256, 0, ms>>>(out, 0);
    }

    // chunks 1..3: wait W, then GEMM + attn (stream order covers own conv)
    for (int c = 1; c < 4; ++c) {
        cudaStream_t st = g_sc.s[c - 1];
        cudaStreamWaitEvent(st, g_sc.evConvW, 0);
        dim3 grid(32, 6, 2);
        qkv_gemm_mma<<<grid, 256, SMEM_GEMM, st>>>(c * 2);
        attn_window8<<<1024, 256, 0, st>>>(out, c * 2);
    }

    // join
    for (int c = 1; c < 4; ++c) {
        cudaEventRecord(g_sc.evJoin[c - 1], g_sc.s[c - 1]);
        cudaStreamWaitEvent(ms, g_sc.evJoin[c - 1], 0);
    }
}

// round 13
// speedup vs baseline: 1.0123x; 1.0123x over previous
#include <cuda_runtime.h>
#include <cuda_bf16.h>
#include <cstdint>

#define BATCH 8
#define CCH   256
#define WID   4096
#define GROUPS 3

// fp32 scratch: qkv[g*256+o][b][j]
__device__ float g_qkv[(size_t)GROUPS * CCH * BATCH * WID];
// pre-split bf16 operands
__device__ __nv_bfloat16 g_xh[(size_t)BATCH * CCH * WID];
__device__ __nv_bfloat16 g_xl[(size_t)BATCH * CCH * WID];
__device__ __nv_bfloat16 g_wh[(size_t)GROUPS * CCH * CCH];
__device__ __nv_bfloat16 g_wl[(size_t)GROUPS * CCH * CCH];

// ---------------------------------------------------------------------------
__device__ __forceinline__ uint32_t sptr(const void* p) {
    return (uint32_t)__cvta_generic_to_shared(p);
}
__device__ __forceinline__ void split2(float f0, float f1, uint32_t& h, uint32_t& l) {
    __nv_bfloat16 h0 = __float2bfloat16(f0);
    __nv_bfloat16 h1 = __float2bfloat16(f1);
    __nv_bfloat16 l0 = __float2bfloat16(f0 - __bfloat162float(h0));
    __nv_bfloat16 l1 = __float2bfloat16(f1 - __bfloat162float(h1));
    h = (uint32_t)__bfloat16_as_ushort(h0) | ((uint32_t)__bfloat16_as_ushort(h1) << 16);
    l = (uint32_t)__bfloat16_as_ushort(l0) | ((uint32_t)__bfloat16_as_ushort(l1) << 16);
}
__device__ __forceinline__ void ldsm_x4(uint32_t addr, uint32_t* r) {
    asm volatile("ldmatrix.sync.aligned.m8n8.x4.shared.b16 {%0,%1,%2,%3}, [%4];"
                 : "=r"(r[0]), "=r"(r[1]), "=r"(r[2]), "=r"(r[3]) : "r"(addr));
}
__device__ __forceinline__ void ldsm_x4_t(uint32_t addr, uint32_t& r0, uint32_t& r1,
                                          uint32_t& r2, uint32_t& r3) {
    asm volatile("ldmatrix.sync.aligned.m8n8.x4.trans.shared.b16 {%0,%1,%2,%3}, [%4];"
                 : "=r"(r0), "=r"(r1), "=r"(r2), "=r"(r3) : "r"(addr));
}
__device__ __forceinline__ void mma16816(float* c, const uint32_t* a,
                                         uint32_t b0, uint32_t b1) {
    asm volatile(
        "mma.sync.aligned.m16n8k16.row.col.f32.bf16.bf16.f32 "
        "{%0,%1,%2,%3}, {%4,%5,%6,%7}, {%8,%9}, {%0,%1,%2,%3};"
        : "+f"(c[0]), "+f"(c[1]), "+f"(c[2]), "+f"(c[3])
        : "r"(a[0]), "r"(a[1]), "r"(a[2]), "r"(a[3]), "r"(b0), "r"(b1));
}
#define CP16(dst, src) \
    asm volatile("cp.async.cg.shared.global [%0], [%1], 16;" :: "r"(dst), "l"(src))
#define CP_COMMIT() asm volatile("cp.async.commit_group;")
#define CP_WAIT(n)  asm volatile("cp.async.wait_group %0;" :: "n"(n))

// ---------------------------------------------------------------------------
// Kernel 0: split fp32 -> bf16 hi/lo; parameterized x-range, optional W part.
// ---------------------------------------------------------------------------
#define NX4 (BATCH * CCH * WID / 4)   // 2097152 float4 in x
#define NW4 (CCH * CCH / 4)           // 16384 float4 per weight
#define NXB (NX4 / 8)                 // 262144 float4 per batch

__global__ __launch_bounds__(256)
void convert_split(const float* __restrict__ x, const float* __restrict__ wq,
                   const float* __restrict__ wk, const float* __restrict__ wv,
                   int nx4, int xbase, int withW)
{
    int idx = blockIdx.x * 256 + threadIdx.x;
    if (idx < nx4) {
        int e = xbase + idx;
        float4 v = ((const float4*)x)[e];
        uint32_t h01, l01, h23, l23;
        split2(v.x, v.y, h01, l01);
        split2(v.z, v.w, h23, l23);
        ((uint2*)g_xh)[e] = make_uint2(h01, h23);
        ((uint2*)g_xl)[e] = make_uint2(l01, l23);
    } else if (withW) {
        int r = idx - nx4;
        if (r < 3 * NW4) {
            int g = r / NW4, e = r % NW4;
            const float* W = (g == 0) ? wq : (g == 1) ? wk : wv;
            float4 v = ((const float4*)W)[e];
            uint32_t h01, l01, h23, l23;
            split2(v.x, v.y, h01, l01);
            split2(v.z, v.w, h23, l23);
            ((uint2*)g_wh)[g * NW4 + e] = make_uint2(h01, h23);
            ((uint2*)g_wl)[g * NW4 + e] = make_uint2(l01, l23);
        }
    }
}

// ---------------------------------------------------------------------------
// Kernel 1: GEMM (R5 design), 3-stage cp.async, pass-major MMA.
// Stage (37888 B): Ah[128][40]@0, Al@10240, Bh[32][136]@20480, Bl@29184
// ---------------------------------------------------------------------------
#define STAGE_BYTES 37888
#define SMEM_GEMM   (3 * STAGE_BYTES)   // 113664

__device__ __forceinline__ void prefetch_chunk(
    char* s, int stage, int tid,
    const __nv_bfloat16* __restrict__ whg, const __nv_bfloat16* __restrict__ wlg,
    const __nv_bfloat16* __restrict__ xhb, const __nv_bfloat16* __restrict__ xlb,
    int kc, int j0)
{
    uint32_t base = sptr(s + stage * STAGE_BYTES);
    #pragma unroll
    for (int i = 0; i < 2; ++i) {
        int e = tid + i * 256;
        int row = e >> 2, seg = e & 3;
        uint32_t off = (uint32_t)(row * 40 + seg * 8) * 2;
        CP16(base + off,         whg + (size_t)row * CCH + kc + seg * 8);
        CP16(base + 10240 + off, wlg + (size_t)row * CCH + kc + seg * 8);
    }
    #pragma unroll
    for (int i = 0; i < 2; ++i) {
        int e = tid + i * 256;
        int row = e >> 4, seg = e & 15;
        uint32_t off = (uint32_t)(row * 136 + seg * 8) * 2;
        CP16(base + 20480 + off, xhb + (size_t)(kc + row) * WID + j0 + seg * 8);
        CP16(base + 29184 + off, xlb + (size_t)(kc + row) * WID + j0 + seg * 8);
    }
}

__global__ __launch_bounds__(256, 2)
void qkv_gemm_mma(int bb)
{
    extern __shared__ char smem[];

    const int nt = blockIdx.x;
    const int my = blockIdx.y;
    const int b  = blockIdx.z + bb;
    const int g  = my >> 1;
    const int m0g = (my & 1) * 128;
    const int j0 = nt * 128;

    const __nv_bfloat16* whg = g_wh + (size_t)g * CCH * CCH + (size_t)m0g * CCH;
    const __nv_bfloat16* wlg = g_wl + (size_t)g * CCH * CCH + (size_t)m0g * CCH;
    const __nv_bfloat16* xhb = g_xh + (size_t)b * CCH * WID;
    const __nv_bfloat16* xlb = g_xl + (size_t)b * CCH * WID;

    const int tid  = threadIdx.x;
    const int lane = tid & 31;
    const int wid  = tid >> 5;
    const int wm   = wid >> 2;
    const int wn   = wid & 3;
    const int ltt  = lane >> 3;
    const int ltr  = lane & 7;

    float acc[4][4][4];
    #pragma unroll
    for (int i = 0; i < 4; ++i)
        #pragma unroll
        for (int j = 0; j < 4; ++j)
            #pragma unroll
            for (int r = 0; r < 4; ++r) acc[i][j][r] = 0.f;

    prefetch_chunk(smem, 0, tid, whg, wlg, xhb, xlb, 0, j0);
    CP_COMMIT();
    prefetch_chunk(smem, 1, tid, whg, wlg, xhb, xlb, 32, j0);
    CP_COMMIT();

    #pragma unroll 1
    for (int kc8 = 0; kc8 < 8; ++kc8) {
        const int stage = kc8 % 3;
        if (kc8 < 7) { CP_WAIT(1); } else { CP_WAIT(0); }
        __syncthreads();

        const char* sbuf = smem + stage * STAGE_BYTES;
        const __nv_bfloat16* Ahp = (const __nv_bfloat16*)(sbuf);
        const __nv_bfloat16* Alp = (const __nv_bfloat16*)(sbuf + 10240);
        const __nv_bfloat16* Bhp = (const __nv_bfloat16*)(sbuf + 20480);
        const __nv_bfloat16* Blp = (const __nv_bfloat16*)(sbuf + 29184);

        #pragma unroll
        for (int ks = 0; ks < 2; ++ks) {
            const int kb = ks * 16;
            uint32_t bh[4][2], bl[4][2];
            #pragma unroll
            for (int np = 0; np < 2; ++np) {
                int krow = kb + (ltt & 1) * 8 + ltr;
                int ncol = wn * 32 + np * 16 + (ltt >> 1) * 8;
                ldsm_x4_t(sptr(Bhp + krow * 136 + ncol),
                          bh[np * 2][0], bh[np * 2][1], bh[np * 2 + 1][0], bh[np * 2 + 1][1]);
                ldsm_x4_t(sptr(Blp + krow * 136 + ncol),
                          bl[np * 2][0], bl[np * 2][1], bl[np * 2 + 1][0], bl[np * 2 + 1][1]);
            }
            uint32_t ah[4][4], al[4][4];
            #pragma unroll
            for (int ma = 0; ma < 4; ++ma) {
                int row = wm * 64 + ma * 16 + (ltt & 1) * 8 + ltr;
                int col = kb + (ltt >> 1) * 8;
                ldsm_x4(sptr(Ahp + row * 40 + col), ah[ma]);
                ldsm_x4(sptr(Alp + row * 40 + col), al[ma]);
            }
            #pragma unroll
            for (int ma = 0; ma < 4; ++ma)
                #pragma unroll
                for (int na = 0; na < 4; ++na)
                    mma16816(acc[ma][na], ah[ma], bh[na][0], bh[na][1]);
            #pragma unroll
            for (int ma = 0; ma < 4; ++ma)
                #pragma unroll
                for (int na = 0; na < 4; ++na)
                    mma16816(acc[ma][na], al[ma], bh[na][0], bh[na][1]);
            #pragma unroll
            for (int ma = 0; ma < 4; ++ma)
                #pragma unroll
                for (int na = 0; na < 4; ++na)
                    mma16816(acc[ma][na], ah[ma], bl[na][0], bl[na][1]);
        }
        __syncthreads();

        if (kc8 < 6) {
            prefetch_chunk(smem, (kc8 + 2) % 3, tid, whg, wlg, xhb, xlb, (kc8 + 2) * 32, j0);
            CP_COMMIT();
        }
    }

    #pragma unroll
    for (int ma = 0; ma < 4; ++ma) {
        int r0 = m0g + wm * 64 + ma * 16 + (lane >> 2);
        #pragma unroll
        for (int na = 0; na < 4; ++na) {
            int jj = j0 + wn * 32 + na * 8 + (lane & 3) * 2;
            float* d0 = g_qkv + ((size_t)(g * 256 + r0) * BATCH + b) * WID + jj;
            float* d1 = d0 + (size_t)8 * BATCH * WID;
            *(float2*)d0 = make_float2(acc[ma][na][0], acc[ma][na][1]);
            *(float2*)d1 = make_float2(acc[ma][na][2], acc[ma][na][3]);
        }
    }
}

// ---------------------------------------------------------------------------
// Kernel 2: windowed softmax, 8 outputs/thread, no max-sub, fast divide.
// Covers batches [bb, bb+count) — grid = count*512 blocks.
// ---------------------------------------------------------------------------
__global__ __launch_bounds__(256)
void attn_window8(float* __restrict__ out, int bb)
{
    int t8 = blockIdx.x * 256 + threadIdx.x;
    int w  = (t8 & 511) * 8;
    int t  = (t8 >> 9) + bb * 256;   // b*256 + o
    int o  = t & 255;
    int b  = t >> 8;

    const float* Q = g_qkv + ((size_t)o * BATCH + b) * WID;
    const float* K = Q + (size_t)256 * BATCH * WID;
    const float* V = Q + (size_t)512 * BATCH * WID;

    const float4 z4 = make_float4(0.f, 0.f, 0.f, 0.f);
    float4 q0 = *(const float4*)(Q + w);
    float4 q1 = *(const float4*)(Q + w + 4);
    float4 km = (w >= 4)      ? *(const float4*)(K + w - 4) : z4;
    float4 k0 = *(const float4*)(K + w);
    float4 k1 = *(const float4*)(K + w + 4);
    float4 kp = (w + 8 < WID) ? *(const float4*)(K + w + 8) : z4;
    float4 vm = (w >= 4)      ? *(const float4*)(V + w - 4) : z4;
    float4 v0 = *(const float4*)(V + w);
    float4 v1 = *(const float4*)(V + w + 4);
    float4 vp = (w + 8 < WID) ? *(const float4*)(V + w + 8) : z4;

    float kk[14] = {km.y, km.z, km.w, k0.x, k0.y, k0.z, k0.w,
                    k1.x, k1.y, k1.z, k1.w, kp.x, kp.y, kp.z};
    float vv[14] = {vm.y, vm.z, vm.w, v0.x, v0.y, v0.z, v0.w,
                    v1.x, v1.y, v1.z, v1.w, vp.x, vp.y, vp.z};
    float qv[8]  = {q0.x, q0.y, q0.z, q0.w, q1.x, q1.y, q1.z, q1.w};

    float res[8];
    #pragma unroll
    for (int tt = 0; tt < 8; ++tt) {
        float sum = 0.f, accn = 0.f;
        #pragma unroll
        for (int i = 0; i < 7; ++i) {
            float e = __expf(qv[tt] * kk[tt + i]);
            sum += e;
            accn = fmaf(e, vv[tt + i], accn);
        }
        res[tt] = __fdividef(accn, sum);
    }
    float* dst = out + (size_t)t * WID + w;
    *(float4*)dst       = make_float4(res[0], res[1], res[2], res[3]);
    *(float4*)(dst + 4) = make_float4(res[4], res[5], res[6], res[7]);
}

// ---------------------------------------------------------------------------
// Stream context (created at load time; no device memory). Chunks 1..3 run on
// priority-ordered side streams (chunk 0 on the capturing main stream).
// ---------------------------------------------------------------------------
namespace {
struct StreamCtx {
    cudaStream_t s[3];
    cudaEvent_t evFork, evConvW, evJoin[3];
    StreamCtx() {
        int lo = 0, hi = 0;
        cudaDeviceGetStreamPriorityRange(&lo, &hi);   // hi = highest (most negative)
        // chunk 1 highest of the three, chunk 3 lowest
        for (int i = 0; i < 3; ++i) {
            int pr = hi + 1 + i;
            if (pr > lo) pr = lo;
            cudaStreamCreateWithPriority(&s[i], cudaStreamNonBlocking, pr);
        }
        cudaEventCreateWithFlags(&evFork,  cudaEventDisableTiming);
        cudaEventCreateWithFlags(&evConvW, cudaEventDisableTiming);
        for (int i = 0; i < 3; ++i)
            cudaEventCreateWithFlags(&evJoin[i], cudaEventDisableTiming);
    }
};
StreamCtx g_sc;

cudaStream_t pick_main_stream() {
    cudaStreamCaptureStatus st = cudaStreamCaptureStatusNone;
    if (cudaStreamGetCaptureInfo(cudaStreamPerThread, &st) == cudaSuccess &&
        st == cudaStreamCaptureStatusActive)
        return cudaStreamPerThread;
    return cudaStreamLegacy;
}
} // namespace

// ---------------------------------------------------------------------------
extern "C" void kernel_launch(void* const* d_in, const int* in_sizes, int n_in,
                              void* d_out, int out_size)
{
    (void)in_sizes; (void)n_in; (void)out_size;
    const float* x  = (const float*)d_in[0];
    const float* wq = (const float*)d_in[1];
    const float* wk = (const float*)d_in[2];
    const float* wv = (const float*)d_in[3];
    float* out = (float*)d_out;

    cudaFuncSetAttribute(qkv_gemm_mma, cudaFuncAttributeMaxDynamicSharedMemorySize, SMEM_GEMM);

    cudaStream_t ms = pick_main_stream();

    // asymmetric chunks: head and tail small
    static const int bstart[4] = {0, 1, 4, 7};
    static const int bcount[4] = {1, 3, 3, 1};

    // fork
    cudaEventRecord(g_sc.evFork, ms);
    for (int i = 0; i < 3; ++i)
        cudaStreamWaitEvent(g_sc.s[i], g_sc.evFork, 0);

    // chunk 0 conversion (W + batch 0) on ms — small head
    convert_split<<<(bcount[0] * NXB + 3 * NW4 + 255) / 256, 256, 0, ms>>>(
        x, wq, wk, wv, bcount[0] * NXB, 0, 1);
    cudaEventRecord(g_sc.evConvW, ms);

    // chunks 1..3 conversion on their streams (x only)
    for (int c = 1; c < 4; ++c)
        convert_split<<<(bcount[c] * NXB) / 256, 256, 0, g_sc.s[c - 1]>>>(
            x, wq, wk, wv, bcount[c] * NXB, bstart[c] * NXB, 0);

    // chunk 0 GEMM + attn on ms
    {
        dim3 grid(32, 6, bcount[0]);
        qkv_gemm_mma<<<grid, 256, SMEM_GEMM, ms>>>(bstart[0]);
        attn_window8<<<bcount[0] * 512, 256, 0, ms>>>(out, bstart[0]);
    }

    // chunks 1..3: wait W event, then GEMM + attn
    for (int c = 1; c < 4; ++c) {
        cudaStream_t st = g_sc.s[c - 1];
        cudaStreamWaitEvent(st, g_sc.evConvW, 0);
        dim3 grid(32, 6, bcount[c]);
        qkv_gemm_mma<<<grid, 256, SMEM_GEMM, st>>>(bstart[c]);
        attn_window8<<<bcount[c] * 512, 256, 0, st>>>(out, bstart[c]);
    }

    // join
    for (int c = 1; c < 4; ++c) {
        cudaEventRecord(g_sc.evJoin[c - 1], g_sc.s[c - 1]);
        cudaStreamWaitEvent(ms, g_sc.evJoin[c - 1], 0);
    }
}